// round 1
// baseline (speedup 1.0000x reference)
#include <cuda_runtime.h>
#include <cuda_bf16.h>

// V[b,n,f,t] = sum_p cos(obs[b,p,f,t] - tpd[b,p,n,f])
//            = sum_p cos(obs)*cos(tpd) + sin(obs)*sin(tpd)
//
// B=4, P=6, N=36, F=257, T=300.
// One block per (b,f). Phase 1: 216 steering sincos -> smem.
// Phase 2: per-thread t, 6 obs sincos -> registers, rank-12 FMA over n.

#define NP   6
#define NDIR 36
#define NF   257
#define NT   300
#define NB   4

__global__ __launch_bounds__(320)
void dirfeat_kernel(const float* __restrict__ obs,     // (B*P, F, T)
                    const float* __restrict__ azi,     // (B, N)
                    const float* __restrict__ ele,     // (B, N)
                    const float* __restrict__ pairs,   // (P, 3)
                    const float* __restrict__ freq,    // (F,)
                    float* __restrict__ out)           // (B, N, F, T)
{
    const int bf = blockIdx.x;
    const int b  = bf / NF;
    const int f  = bf - b * NF;
    const int tid = threadIdx.x;

    // cs[n][p] = {cos(tpd), sin(tpd)} for this (b,f)
    __shared__ float2 cs[NDIR][NP];

    if (tid < NDIR * NP) {
        const int n = tid / NP;
        const int p = tid - n * NP;
        const float a = azi[b * NDIR + n];
        const float e = ele[b * NDIR + n];
        float sa, ca, se, ce;
        __sincosf(a, &sa, &ca);
        __sincosf(e, &se, &ce);
        const float rx = se * ca;
        const float ry = se * sa;
        const float rz = ce;
        const float dot = pairs[p * 3 + 0] * rx
                        + pairs[p * 3 + 1] * ry
                        + pairs[p * 3 + 2] * rz;
        // tpd = 2*pi * dot/343 * freq[f]
        const float tpd = (6.283185307179586f / 343.0f) * dot * freq[f];
        float s, c;
        __sincosf(tpd, &s, &c);
        cs[n][p] = make_float2(c, s);
    }
    __syncthreads();

    const int t = tid;
    if (t < NT) {
        float co[NP], so[NP];
#pragma unroll
        for (int p = 0; p < NP; p++) {
            const float o = obs[((b * NP + p) * NF + f) * NT + t];
            __sincosf(o, &so[p], &co[p]);
        }

        float* outp = out + ((long long)(b * NDIR) * NF + f) * NT + t;
#pragma unroll
        for (int n = 0; n < NDIR; n++) {
            float acc = 0.0f;
#pragma unroll
            for (int p = 0; p < NP; p++) {
                const float2 v = cs[n][p];
                acc = fmaf(co[p], v.x, acc);
                acc = fmaf(so[p], v.y, acc);
            }
            outp[(long long)n * NF * NT] = acc;
        }
    }
}

extern "C" void kernel_launch(void* const* d_in, const int* in_sizes, int n_in,
                              void* d_out, int out_size) {
    const float* obs   = (const float*)d_in[0];
    const float* azi   = (const float*)d_in[1];
    const float* ele   = (const float*)d_in[2];
    const float* pairs = (const float*)d_in[3];
    const float* freq  = (const float*)d_in[4];
    float* out = (float*)d_out;

    dim3 grid(NB * NF);   // 1028 blocks: one per (b,f)
    dim3 block(320);      // 10 warps; t = tid < 300 active in phase 2
    dirfeat_kernel<<<grid, block>>>(obs, azi, ele, pairs, freq, out);
}

// round 2
// speedup vs baseline: 1.1514x; 1.1514x over previous
#include <cuda_runtime.h>
#include <cuda_bf16.h>

// V[b,n,f,t] = sum_p cos(obs[b,p,f,t] - tpd[b,p,n,f])
//            = sum_p cos(obs)*cos(tpd) + sin(obs)*sin(tpd)
//
// B=4, P=6, N=36, F=257, T=300.
// Block covers (b, 2 freq bins). Phase 1: 432 steering sincos -> smem.
// Phase 2: each thread owns one (f_local, 4-t quad): float4 obs load,
// 24 sincos, then per-n: 3 LDS.128 + 48 FMA + 1 STG.128.

#define NP    6
#define NDIR  36
#define NF    257
#define NT    300
#define NB    4
#define FPB   2            // freq bins per block
#define NFB   129          // ceil(257/2)
#define NTQ   75           // t-quads (300/4)

__global__ __launch_bounds__(160)
void dirfeat_kernel(const float* __restrict__ obs,     // (B*P, F, T)
                    const float* __restrict__ azi,     // (B, N)
                    const float* __restrict__ ele,     // (B, N)
                    const float* __restrict__ pairs,   // (P, 3)
                    const float* __restrict__ freq,    // (F,)
                    float* __restrict__ out)           // (B, N, F, T)
{
    const int b  = blockIdx.x / NFB;
    const int f0 = (blockIdx.x - b * NFB) * FPB;
    const int tid = threadIdx.x;

    // cs[fl][n][2p] = cos(tpd), cs[fl][n][2p+1] = sin(tpd)
    __shared__ __align__(16) float cs[FPB][NDIR][2 * NP];

    // ---- Phase 1: 432 steering entries across 160 threads ----
    for (int e = tid; e < FPB * NDIR * NP; e += 160) {
        const int fl = e / (NDIR * NP);
        const int r  = e - fl * (NDIR * NP);
        const int n  = r / NP;
        const int p  = r - n * NP;
        const int f  = f0 + fl;
        if (f < NF) {
            const float a  = azi[b * NDIR + n];
            const float el = ele[b * NDIR + n];
            float sa, ca, se, ce;
            __sincosf(a,  &sa, &ca);
            __sincosf(el, &se, &ce);
            const float rx = se * ca, ry = se * sa, rz = ce;
            const float dot = pairs[p * 3 + 0] * rx
                            + pairs[p * 3 + 1] * ry
                            + pairs[p * 3 + 2] * rz;
            const float tpd = (6.283185307179586f / 343.0f) * dot * freq[f];
            float s, c;
            __sincosf(tpd, &s, &c);
            cs[fl][n][2 * p]     = c;
            cs[fl][n][2 * p + 1] = s;
        }
    }
    __syncthreads();

    // ---- Phase 2: threads 0..149 -> (fl, t-quad) ----
    if (tid < FPB * NTQ) {
        const int fl = tid / NTQ;
        const int tq = tid - fl * NTQ;
        const int f  = f0 + fl;
        if (f < NF) {
            const int t0 = tq * 4;

            float co[NP][4], so[NP][4];
#pragma unroll
            for (int p = 0; p < NP; p++) {
                const float4 o = *reinterpret_cast<const float4*>(
                    obs + ((long long)(b * NP + p) * NF + f) * NT + t0);
                __sincosf(o.x, &so[p][0], &co[p][0]);
                __sincosf(o.y, &so[p][1], &co[p][1]);
                __sincosf(o.z, &so[p][2], &co[p][2]);
                __sincosf(o.w, &so[p][3], &co[p][3]);
            }

            float* outp = out + ((long long)(b * NDIR) * NF + f) * NT + t0;
            const long long nstride = (long long)NF * NT;

#pragma unroll
            for (int n = 0; n < NDIR; n++) {
                const float4* c4 = reinterpret_cast<const float4*>(cs[fl][n]);
                const float4 v0 = c4[0];   // c0 s0 c1 s1
                const float4 v1 = c4[1];   // c2 s2 c3 s3
                const float4 v2 = c4[2];   // c4 s4 c5 s5

                float a0 = 0.f, a1 = 0.f, a2 = 0.f, a3 = 0.f;
                // p = 0
                a0 = fmaf(co[0][0], v0.x, a0); a0 = fmaf(so[0][0], v0.y, a0);
                a1 = fmaf(co[0][1], v0.x, a1); a1 = fmaf(so[0][1], v0.y, a1);
                a2 = fmaf(co[0][2], v0.x, a2); a2 = fmaf(so[0][2], v0.y, a2);
                a3 = fmaf(co[0][3], v0.x, a3); a3 = fmaf(so[0][3], v0.y, a3);
                // p = 1
                a0 = fmaf(co[1][0], v0.z, a0); a0 = fmaf(so[1][0], v0.w, a0);
                a1 = fmaf(co[1][1], v0.z, a1); a1 = fmaf(so[1][1], v0.w, a1);
                a2 = fmaf(co[1][2], v0.z, a2); a2 = fmaf(so[1][2], v0.w, a2);
                a3 = fmaf(co[1][3], v0.z, a3); a3 = fmaf(so[1][3], v0.w, a3);
                // p = 2
                a0 = fmaf(co[2][0], v1.x, a0); a0 = fmaf(so[2][0], v1.y, a0);
                a1 = fmaf(co[2][1], v1.x, a1); a1 = fmaf(so[2][1], v1.y, a1);
                a2 = fmaf(co[2][2], v1.x, a2); a2 = fmaf(so[2][2], v1.y, a2);
                a3 = fmaf(co[2][3], v1.x, a3); a3 = fmaf(so[2][3], v1.y, a3);
                // p = 3
                a0 = fmaf(co[3][0], v1.z, a0); a0 = fmaf(so[3][0], v1.w, a0);
                a1 = fmaf(co[3][1], v1.z, a1); a1 = fmaf(so[3][1], v1.w, a1);
                a2 = fmaf(co[3][2], v1.z, a2); a2 = fmaf(so[3][2], v1.w, a2);
                a3 = fmaf(co[3][3], v1.z, a3); a3 = fmaf(so[3][3], v1.w, a3);
                // p = 4
                a0 = fmaf(co[4][0], v2.x, a0); a0 = fmaf(so[4][0], v2.y, a0);
                a1 = fmaf(co[4][1], v2.x, a1); a1 = fmaf(so[4][1], v2.y, a1);
                a2 = fmaf(co[4][2], v2.x, a2); a2 = fmaf(so[4][2], v2.y, a2);
                a3 = fmaf(co[4][3], v2.x, a3); a3 = fmaf(so[4][3], v2.y, a3);
                // p = 5
                a0 = fmaf(co[5][0], v2.z, a0); a0 = fmaf(so[5][0], v2.w, a0);
                a1 = fmaf(co[5][1], v2.z, a1); a1 = fmaf(so[5][1], v2.w, a1);
                a2 = fmaf(co[5][2], v2.z, a2); a2 = fmaf(so[5][2], v2.w, a2);
                a3 = fmaf(co[5][3], v2.z, a3); a3 = fmaf(so[5][3], v2.w, a3);

                *reinterpret_cast<float4*>(outp + (long long)n * nstride) =
                    make_float4(a0, a1, a2, a3);
            }
        }
    }
}

extern "C" void kernel_launch(void* const* d_in, const int* in_sizes, int n_in,
                              void* d_out, int out_size) {
    const float* obs   = (const float*)d_in[0];
    const float* azi   = (const float*)d_in[1];
    const float* ele   = (const float*)d_in[2];
    const float* pairs = (const float*)d_in[3];
    const float* freq  = (const float*)d_in[4];
    float* out = (float*)d_out;

    dim3 grid(NB * NFB);   // 516 blocks: (b, f-pair)
    dim3 block(160);       // 5 warps
    dirfeat_kernel<<<grid, block>>>(obs, azi, ele, pairs, freq, out);
}

// round 4
// speedup vs baseline: 1.3464x; 1.1693x over previous
#include <cuda_runtime.h>
#include <cuda_bf16.h>

// V[b,n,f,t] = sum_p cos(obs[b,p,f,t] - tpd[b,p,n,f])
// Pair-vector degeneracy (4-mic square): pairs[3]==pairs[2], pairs[5]==-pairs[0]
// -> 4 distinct phase vectors (rep pair indices 0,1,2,4), 8 FMA per output:
//   V = (co0+co5)c0 + (so0-so5)s0 + co1*c1 + so1*s1
//     + (co2+co3)c2 + (so2+so3)s2 + co4*c3 + so4*s3
//
// B=4, P=6, N=36, F=257, T=300.
// One block per (b,f), 160 threads. Phase 1: 144 steering sincos -> smem
// (36 n x 4 groups x {cos,sin}). Phase 2: 150 threads = 2 n-halves x 75
// t-quads; each thread: float4 obs loads, 24 sincos, combine to 8x4 regs,
// then 18 n-iters of (2 LDS.128 + 32 FFMA + 1 STG.128).

#define NP    6
#define NG    4            // distinct phase groups
#define NDIR  36
#define NF    257
#define NT    300
#define NB    4
#define NTQ   75           // t-quads
#define NH    2            // n-halves
#define NPH   18           // n per half

__global__ __launch_bounds__(160)
void dirfeat_kernel(const float* __restrict__ obs,     // (B*P, F, T)
                    const float* __restrict__ azi,     // (B, N)
                    const float* __restrict__ ele,     // (B, N)
                    const float* __restrict__ pairs,   // (P, 3)
                    const float* __restrict__ freq,    // (F,)
                    float* __restrict__ out)           // (B, N, F, T)
{
    const int b  = blockIdx.x / NF;
    const int f  = blockIdx.x - b * NF;
    const int tid = threadIdx.x;

    // cs[n][2g] = cos(tau_g), cs[n][2g+1] = sin(tau_g)
    __shared__ __align__(16) float cs[NDIR][2 * NG];

    // ---- Phase 1: 144 steering entries ----
    if (tid < NDIR * NG) {
        const int n = tid >> 2;          // tid / 4
        const int g = tid & 3;           // tid % 4
        const int rep = (g == 3) ? 4 : g;  // rep pair indices {0,1,2,4}

        const float a  = azi[b * NDIR + n];
        const float el = ele[b * NDIR + n];
        float sa, ca, se, ce;
        __sincosf(a,  &sa, &ca);
        __sincosf(el, &se, &ce);
        const float rx = se * ca, ry = se * sa, rz = ce;
        const float dot = pairs[rep * 3 + 0] * rx
                        + pairs[rep * 3 + 1] * ry
                        + pairs[rep * 3 + 2] * rz;
        const float tau = (6.283185307179586f / 343.0f) * dot * freq[f];
        float s, c;
        __sincosf(tau, &s, &c);
        cs[n][2 * g]     = c;
        cs[n][2 * g + 1] = s;
    }
    __syncthreads();

    // ---- Phase 2 ----
    if (tid < NH * NTQ) {
        const int h  = tid / NTQ;        // n-half
        const int tq = tid - h * NTQ;
        const int t0 = tq * 4;

        const long long obs_p_stride = (long long)NF * NT;
        const float* obase = obs + ((long long)b * NP * NF + f) * NT + t0;

        // Combined obs terms: uc[g][j], us[g][j]
        float uc[NG][4], us[NG][4];

        {   // group 0: pairs 0 and 5 (negated vector -> sin difference)
            const float4 oA = *reinterpret_cast<const float4*>(obase + 0 * obs_p_stride);
            const float4 oB = *reinterpret_cast<const float4*>(obase + 5 * obs_p_stride);
            float sA, cA, sB, cB;
            __sincosf(oA.x, &sA, &cA); __sincosf(oB.x, &sB, &cB);
            uc[0][0] = cA + cB; us[0][0] = sA - sB;
            __sincosf(oA.y, &sA, &cA); __sincosf(oB.y, &sB, &cB);
            uc[0][1] = cA + cB; us[0][1] = sA - sB;
            __sincosf(oA.z, &sA, &cA); __sincosf(oB.z, &sB, &cB);
            uc[0][2] = cA + cB; us[0][2] = sA - sB;
            __sincosf(oA.w, &sA, &cA); __sincosf(oB.w, &sB, &cB);
            uc[0][3] = cA + cB; us[0][3] = sA - sB;
        }
        {   // group 2: pairs 2 and 3 (identical vector -> sum)
            const float4 oA = *reinterpret_cast<const float4*>(obase + 2 * obs_p_stride);
            const float4 oB = *reinterpret_cast<const float4*>(obase + 3 * obs_p_stride);
            float sA, cA, sB, cB;
            __sincosf(oA.x, &sA, &cA); __sincosf(oB.x, &sB, &cB);
            uc[2][0] = cA + cB; us[2][0] = sA + sB;
            __sincosf(oA.y, &sA, &cA); __sincosf(oB.y, &sB, &cB);
            uc[2][1] = cA + cB; us[2][1] = sA + sB;
            __sincosf(oA.z, &sA, &cA); __sincosf(oB.z, &sB, &cB);
            uc[2][2] = cA + cB; us[2][2] = sA + sB;
            __sincosf(oA.w, &sA, &cA); __sincosf(oB.w, &sB, &cB);
            uc[2][3] = cA + cB; us[2][3] = sA + sB;
        }
        {   // group 1: pair 1 alone
            const float4 o = *reinterpret_cast<const float4*>(obase + 1 * obs_p_stride);
            __sincosf(o.x, &us[1][0], &uc[1][0]);
            __sincosf(o.y, &us[1][1], &uc[1][1]);
            __sincosf(o.z, &us[1][2], &uc[1][2]);
            __sincosf(o.w, &us[1][3], &uc[1][3]);
        }
        {   // group 3: pair 4 alone
            const float4 o = *reinterpret_cast<const float4*>(obase + 4 * obs_p_stride);
            __sincosf(o.x, &us[3][0], &uc[3][0]);
            __sincosf(o.y, &us[3][1], &uc[3][1]);
            __sincosf(o.z, &us[3][2], &uc[3][2]);
            __sincosf(o.w, &us[3][3], &uc[3][3]);
        }

        const long long nstride = (long long)NF * NT;
        float* outp = out + (((long long)b * NDIR + h * NPH) * NF + f) * NT + t0;
        const float4* cp = reinterpret_cast<const float4*>(&cs[h * NPH][0]);

#pragma unroll
        for (int i = 0; i < NPH; i++) {
            const float4 w0 = cp[2 * i];       // c0 s0 c1 s1
            const float4 w1 = cp[2 * i + 1];   // c2 s2 c3 s3

            float a0, a1, a2, a3;
            a0 = uc[0][0] * w0.x;               a1 = uc[0][1] * w0.x;
            a2 = uc[0][2] * w0.x;               a3 = uc[0][3] * w0.x;
            a0 = fmaf(us[0][0], w0.y, a0);      a1 = fmaf(us[0][1], w0.y, a1);
            a2 = fmaf(us[0][2], w0.y, a2);      a3 = fmaf(us[0][3], w0.y, a3);
            a0 = fmaf(uc[1][0], w0.z, a0);      a1 = fmaf(uc[1][1], w0.z, a1);
            a2 = fmaf(uc[1][2], w0.z, a2);      a3 = fmaf(uc[1][3], w0.z, a3);
            a0 = fmaf(us[1][0], w0.w, a0);      a1 = fmaf(us[1][1], w0.w, a1);
            a2 = fmaf(us[1][2], w0.w, a2);      a3 = fmaf(us[1][3], w0.w, a3);
            a0 = fmaf(uc[2][0], w1.x, a0);      a1 = fmaf(uc[2][1], w1.x, a1);
            a2 = fmaf(uc[2][2], w1.x, a2);      a3 = fmaf(uc[2][3], w1.x, a3);
            a0 = fmaf(us[2][0], w1.y, a0);      a1 = fmaf(us[2][1], w1.y, a1);
            a2 = fmaf(us[2][2], w1.y, a2);      a3 = fmaf(us[2][3], w1.y, a3);
            a0 = fmaf(uc[3][0], w1.z, a0);      a1 = fmaf(uc[3][1], w1.z, a1);
            a2 = fmaf(uc[3][2], w1.z, a2);      a3 = fmaf(uc[3][3], w1.z, a3);
            a0 = fmaf(us[3][0], w1.w, a0);      a1 = fmaf(us[3][1], w1.w, a1);
            a2 = fmaf(us[3][2], w1.w, a2);      a3 = fmaf(us[3][3], w1.w, a3);

            *reinterpret_cast<float4*>(outp + (long long)i * nstride) =
                make_float4(a0, a1, a2, a3);
        }
    }
}

extern "C" void kernel_launch(void* const* d_in, const int* in_sizes, int n_in,
                              void* d_out, int out_size) {
    const float* obs   = (const float*)d_in[0];
    const float* azi   = (const float*)d_in[1];
    const float* ele   = (const float*)d_in[2];
    const float* pairs = (const float*)d_in[3];
    const float* freq  = (const float*)d_in[4];
    float* out = (float*)d_out;

    dim3 grid(NB * NF);   // 1028 blocks: one per (b,f)
    dim3 block(160);      // 10 warps
    dirfeat_kernel<<<grid, block>>>(obs, azi, ele, pairs, freq, out);
}